// round 1
// baseline (speedup 1.0000x reference)
#include <cuda_runtime.h>
#include <math.h>

// RotorQuantMSE: per-row normalize -> per-group(3) rotor rotation -> 16-level
// uniform quantize -> dequant -> inverse rotation -> rescale.
// N=8192 rows, d=768 (G=256 groups), K=16 centroids.
//
// One block per row, G=256 threads. Row staged through shared memory for
// coalesced float4 global traffic (stride-3 smem access is bank-conflict-free).

#define D_MAX 768
#define G_MAX 256
#define K_MAX 16

__device__ __forceinline__ void rotor_apply(
    float r0, float b1, float b2, float b3,
    float v1, float v2, float v3,
    float& o1, float& o2, float& o3)
{
    // t = R * v   (geometric product, v pure vector)
    float t1 = fmaf(r0, v1, fmaf(b1, v2,  b2 * v3));
    float t2 = fmaf(r0, v2, fmaf(-b1, v1, b3 * v3));
    float t3 = fmaf(r0, v3, fmaf(-b2, v1, -b3 * v2));
    float t7 = fmaf(b1, v3, fmaf(-b2, v2,  b3 * v1));
    // u = t * ~R  (grade-1 part)
    o1 = fmaf(r0, t1, fmaf( b1, t2, fmaf( b2, t3,  b3 * t7)));
    o2 = fmaf(r0, t2, fmaf(-b1, t1, fmaf( b3, t3, -b2 * t7)));
    o3 = fmaf(r0, t3, fmaf(-b2, t1, fmaf(-b3, t2,  b1 * t7)));
}

__global__ void __launch_bounds__(G_MAX)
rotor_quant_kernel(const float* __restrict__ x,
                   const float* __restrict__ centroids,
                   const float* __restrict__ rotors,
                   float* __restrict__ xhat,
                   float* __restrict__ idx_out,
                   float* __restrict__ norms_out,
                   int d)
{
    const int n = blockIdx.x;
    const int t = threadIdx.x;          // group id, 0..255

    __shared__ float sx[D_MAX];         // row staging (in, then x_hat out)
    __shared__ float sidx[D_MAX];       // idx staging (as float)
    __shared__ float sc[K_MAX];
    __shared__ float swarp[8];
    __shared__ float snorm;

    const int nvec4 = d >> 2;           // 192
    const float4* xrow = reinterpret_cast<const float4*>(x + (size_t)n * d);
    if (t < nvec4) reinterpret_cast<float4*>(sx)[t] = xrow[t];
    if (t < K_MAX) sc[t] = centroids[t];
    __syncthreads();

    // per-thread 3-vector
    float v1 = sx[3 * t + 0];
    float v2 = sx[3 * t + 1];
    float v3 = sx[3 * t + 2];

    // row L2-norm reduction
    float sq = fmaf(v1, v1, fmaf(v2, v2, v3 * v3));
    #pragma unroll
    for (int o = 16; o; o >>= 1) sq += __shfl_xor_sync(0xffffffffu, sq, o);
    if ((t & 31) == 0) swarp[t >> 5] = sq;
    __syncthreads();
    if (t < 8) {
        float s = swarp[t];
        #pragma unroll
        for (int o = 4; o; o >>= 1) s += __shfl_xor_sync(0xffu, s, o);
        if (t == 0) snorm = fmaxf(sqrtf(s), 1e-8f);
    }
    __syncthreads();
    const float nrm = snorm;
    const float inv = 1.0f / nrm;

    // rotor for this group
    const float* r = rotors + (size_t)t * 8;
    const float r0 = __ldg(r + 0);
    const float b1 = __ldg(r + 4);
    const float b2 = __ldg(r + 5);
    const float b3 = __ldg(r + 6);

    // forward rotation of unit vector
    float y1, y2, y3;
    rotor_apply(r0, b1, b2, b3, v1 * inv, v2 * inv, v3 * inv, y1, y2, y3);

    // quantize: argmin |y - c_k|, ties -> lower index.
    // c_k = -1 + 2k/15 ; u = (y+1)*7.5 ; k = clamp(ceil(u - 0.5), 0, 15)
    auto quant = [](float y) -> int {
        float u = (y + 1.0f) * 7.5f;
        int k = (int)ceilf(u - 0.5f);
        return max(0, min(15, k));
    };
    int k1 = quant(y1), k2 = quant(y2), k3 = quant(y3);
    float q1 = sc[k1], q2 = sc[k2], q3 = sc[k3];

    // inverse rotation (rotor reversed: b -> -b), rescale
    float h1, h2, h3;
    rotor_apply(r0, -b1, -b2, -b3, q1, q2, q3, h1, h2, h3);

    sx[3 * t + 0] = h1 * nrm;
    sx[3 * t + 1] = h2 * nrm;
    sx[3 * t + 2] = h3 * nrm;
    if (idx_out) {
        sidx[3 * t + 0] = (float)k1;
        sidx[3 * t + 1] = (float)k2;
        sidx[3 * t + 2] = (float)k3;
    }
    __syncthreads();

    if (t < nvec4) {
        reinterpret_cast<float4*>(xhat + (size_t)n * d)[t] =
            reinterpret_cast<float4*>(sx)[t];
        if (idx_out)
            reinterpret_cast<float4*>(idx_out + (size_t)n * d)[t] =
                reinterpret_cast<float4*>(sidx)[t];
    }
    if (t == 0 && norms_out) norms_out[n] = nrm;
}

extern "C" void kernel_launch(void* const* d_in, const int* in_sizes, int n_in,
                              void* d_out, int out_size)
{
    const float* x         = (const float*)d_in[0];   // [N, d]
    const float* centroids = (const float*)d_in[1];   // [K=16]
    const float* rotors    = (const float*)d_in[2];   // [G, 8]

    const int G = in_sizes[2] / 8;        // 256
    const int d = 3 * G;                  // 768
    const int N = in_sizes[0] / d;        // 8192

    float* out   = (float*)d_out;
    float* xhat  = out;
    float* idxp  = nullptr;
    float* normp = nullptr;
    const long nd = (long)N * d;
    if ((long)out_size >= 2 * nd)     idxp  = out + nd;
    if ((long)out_size >= 2 * nd + N) normp = out + 2 * nd;

    rotor_quant_kernel<<<N, G>>>(x, centroids, rotors, xhat, idxp, normp, d);
}